// round 3
// baseline (speedup 1.0000x reference)
#include <cuda_runtime.h>
#include <math.h>
#include <stdint.h>

// Problem constants
#define T_STEPS 512
#define NBATCH  1024
#define IDIM    64
#define RDIM    256
#define NCTA    128
#define NTHR    256
#define BM      64   // batch rows per CTA
#define BN      32   // output cols per CTA

// -------- global scratch (no cudaMalloc allowed) --------
__device__ float g_h[NBATCH * RDIM];       // hidden state [1024][256]
__device__ float g_cat[NBATCH * 2 * RDIM]; // concat buffer [1024][512]
__device__ float g_m[NBATCH * RDIM];       // meshup output [1024][256]
__device__ float g_r1p[8 * NBATCH];        // regressor partials per col-tile
__device__ unsigned g_bar_count = 0;
__device__ unsigned g_bar_gen = 0;

// -------- cp.async helpers (16B, L1-bypass for cross-CTA coherence) --------
__device__ __forceinline__ void cp_async16(float* sdst, const float* gsrc) {
    unsigned s = (unsigned)__cvta_generic_to_shared(sdst);
    asm volatile("cp.async.cg.shared.global [%0], [%1], 16;" :: "r"(s), "l"(gsrc));
}
__device__ __forceinline__ void cp_commit() {
    asm volatile("cp.async.commit_group;");
}
template <int N>
__device__ __forceinline__ void cp_wait() {
    asm volatile("cp.async.wait_group %0;" :: "n"(N));
}

// -------- grid-wide sense-reversing barrier --------
__device__ __forceinline__ void grid_barrier() {
    __threadfence();
    __syncthreads();
    if (threadIdx.x == 0) {
        unsigned g = *((volatile unsigned*)&g_bar_gen);
        unsigned old = atomicAdd(&g_bar_count, 1u);
        if (old == NCTA - 1) {
            g_bar_count = 0;
            __threadfence();
            *((volatile unsigned*)&g_bar_gen) = g + 1;
        } else {
            unsigned cur;
            do {
                asm volatile("ld.acquire.gpu.global.u32 %0, [%1];"
                             : "=r"(cur) : "l"(&g_bar_gen));
            } while (cur == g);
        }
    }
    __syncthreads();
}

// -------- stage one 64x64 chunk of A into smem via cp.async (one group) --------
__device__ __forceinline__ void stage_chunk(float* As, const float* __restrict__ Ag,
                                            int lda, int row0, int k0) {
    #pragma unroll
    for (int i = threadIdx.x; i < 1024; i += NTHR) {
        int r = i >> 4;
        int kk = (i & 15) << 2;
        cp_async16(As + r * 64 + kk, Ag + (size_t)(row0 + r) * lda + k0 + kk);
    }
    cp_commit();
}

// -------- compute one staged 64-k chunk: acc[8] over (8 rows x 1 col) --------
template <bool FUSE2>
__device__ __forceinline__ void compute_chunk(
    const float* __restrict__ As,
    const float* __restrict__ Ws1, const float* __restrict__ Ws2,
    int k0, float acc1[8], float acc2[8], int c, int rbase)
{
    #pragma unroll
    for (int kk = 0; kk < 64; kk += 4) {
        float4 af[8];
        #pragma unroll
        for (int j = 0; j < 8; j++)
            af[j] = *(const float4*)(As + (rbase + j) * 64 + kk);
        #pragma unroll
        for (int q = 0; q < 4; q++) {
            float w1 = Ws1[(k0 + kk + q) * BN + c];
            float w2 = 0.f;
            if constexpr (FUSE2) w2 = Ws2[(k0 + kk + q) * BN + c];
            #pragma unroll
            for (int j = 0; j < 8; j++) {
                float a = (q == 0) ? af[j].x : (q == 1) ? af[j].y : (q == 2) ? af[j].z : af[j].w;
                acc1[j] = fmaf(a, w1, acc1[j]);
                if constexpr (FUSE2) acc2[j] = fmaf(a, w2, acc2[j]);
            }
        }
    }
}

// -------- double-buffered pipelined GEMM over NCH 64-k chunks --------
template <int NCH, bool FUSE2>
__device__ __forceinline__ void gemm_pipe(
    const float* __restrict__ Ag, int lda, int row0,
    const float* __restrict__ Ws1, const float* __restrict__ Ws2,
    float* As0, float* As1,
    float acc1[8], float acc2[8], int c, int rbase)
{
    stage_chunk(As0, Ag, lda, row0, 0);
    if (NCH > 1) stage_chunk(As1, Ag, lda, row0, 64);
    #pragma unroll
    for (int i = 0; i < NCH; i++) {
        if (i + 1 < NCH) cp_wait<1>(); else cp_wait<0>();
        __syncthreads();
        compute_chunk<FUSE2>((i & 1) ? As1 : As0, Ws1, Ws2, i * 64, acc1, acc2, c, rbase);
        __syncthreads();
        if (i + 2 < NCH) stage_chunk((i & 1) ? As1 : As0, Ag, lda, row0, (i + 2) * 64);
    }
}

__global__ void __launch_bounds__(NTHR, 1)
recurrent_kernel(const float* __restrict__ inputs,
                 const float* __restrict__ Whp, const float* __restrict__ bhp,
                 const float* __restrict__ Wcp, const float* __restrict__ bcp,
                 const float* __restrict__ Wm,  const float* __restrict__ bm,
                 const float* __restrict__ Whpost, const float* __restrict__ bhpost,
                 const float* __restrict__ Wr1, const float* __restrict__ br1,
                 const float* __restrict__ Wr2, const float* __restrict__ br2,
                 float* __restrict__ out)
{
    extern __shared__ float smem[];
    float* Whp_s    = smem;                   // 256*32
    float* Wm_s     = Whp_s    + 256 * BN;    // 512*32
    float* Whpost_s = Wm_s     + 512 * BN;    // 256*32
    float* Wr1_s    = Whpost_s + 256 * BN;    // 256*32
    float* Wcp_s    = Wr1_s    + 256 * BN;    // 64*32
    float* bias_s   = Wcp_s    + 64 * BN;     // 192 floats
    float* As0      = bias_s   + 192;         // 64*64 staging buf 0
    float* As1      = As0      + 4096;        // 64*64 staging buf 1
    float* Xbuf     = As1      + 4096;        // 64*64 x_t prefetch

    const int tid  = threadIdx.x;
    const int bi   = blockIdx.x >> 3;   // batch-row tile 0..15
    const int bj   = blockIdx.x & 7;    // col tile 0..7
    const int row0 = bi * BM;
    const int c0   = bj * BN;
    const int c    = tid & 31;          // lane == output col within tile
    const int rbase = (tid >> 5) * 8;   // 8 rows per thread

    // ---- load resident weight slices ----
    for (int i = tid; i < 256 * BN; i += NTHR) {
        int k = i >> 5, cc = i & 31;
        Whp_s[i]    = Whp[k * RDIM + c0 + cc];
        Whpost_s[i] = Whpost[k * RDIM + c0 + cc];
        Wr1_s[i]    = Wr1[k * RDIM + c0 + cc];
    }
    for (int i = tid; i < 512 * BN; i += NTHR)
        Wm_s[i] = Wm[(i >> 5) * RDIM + c0 + (i & 31)];
    for (int i = tid; i < 64 * BN; i += NTHR)
        Wcp_s[i] = Wcp[(i >> 5) * RDIM + c0 + (i & 31)];
    if (tid < 32) {
        bias_s[tid]       = bhp[c0 + tid];
        bias_s[32 + tid]  = bcp[c0 + tid];
        bias_s[64 + tid]  = bm[c0 + tid];
        bias_s[96 + tid]  = bhpost[c0 + tid];
        bias_s[128 + tid] = br1[c0 + tid];
        bias_s[160 + tid] = Wr2[c0 + tid];   // Wr2 is (256,1)
    }
    const float br2v = __ldg(br2);
    __syncthreads();

    for (int t = 0; t < T_STEPS; t++) {
        // ---- prefetch x_t (external, read-only: no barrier needed) ----
        stage_chunk(Xbuf, inputs + (size_t)t * NBATCH * IDIM, IDIM, row0, 0);

        // ================= Phase A =================
        // S1: a = tanh(h @ Whp + bhp) -> cat[:, 0:256]
        // S4 (lagged): r1 = relu(h @ Wr1 + br1); partials of r1 @ Wr2
        // S0: tcp = tanh(x_t @ Wcp + bcp) -> cat[:, 256:512]  (computed first,
        //     from the prefetched Xbuf, covering A0/A1 staging latency)
        if (t > 0) {
            float acc_a[8], acc_r1[8], acc_cp[8];
            #pragma unroll
            for (int j = 0; j < 8; j++) {
                acc_a[j]  = bias_s[c];
                acc_r1[j] = bias_s[128 + c];
                acc_cp[j] = bias_s[32 + c];
            }
            stage_chunk(As0, g_h, RDIM, row0, 0);
            stage_chunk(As1, g_h, RDIM, row0, 64);
            cp_wait<2>();          // X done (A0/A1 may still be in flight)
            __syncthreads();
            compute_chunk<false>(Xbuf, Wcp_s, (const float*)0, 0, acc_cp, acc_cp, c, rbase);
            #pragma unroll
            for (int j = 0; j < 8; j++)
                g_cat[(size_t)(row0 + rbase + j) * (2 * RDIM) + RDIM + c0 + c] = tanhf(acc_cp[j]);

            #pragma unroll
            for (int i = 0; i < 4; i++) {
                if (i < 3) cp_wait<1>(); else cp_wait<0>();
                __syncthreads();
                compute_chunk<true>((i & 1) ? As1 : As0, Whp_s, Wr1_s, i * 64,
                                    acc_a, acc_r1, c, rbase);
                __syncthreads();
                if (i + 2 < 4) stage_chunk((i & 1) ? As1 : As0, g_h, RDIM, row0, (i + 2) * 64);
            }
            float w2 = bias_s[160 + c];
            #pragma unroll
            for (int j = 0; j < 8; j++) {
                g_cat[(size_t)(row0 + rbase + j) * (2 * RDIM) + c0 + c] = tanhf(acc_a[j]);
                float v = fmaxf(acc_r1[j], 0.f) * w2;
                #pragma unroll
                for (int off = 16; off > 0; off >>= 1)
                    v += __shfl_down_sync(0xffffffffu, v, off);
                if (c == 0) g_r1p[bj * NBATCH + row0 + rbase + j] = v;
            }
        } else {
            // h0 == 0 -> a = tanh(bhp); S0 from prefetched X
            float acc_cp[8];
            #pragma unroll
            for (int j = 0; j < 8; j++) acc_cp[j] = bias_s[32 + c];
            cp_wait<0>();
            __syncthreads();
            compute_chunk<false>(Xbuf, Wcp_s, (const float*)0, 0, acc_cp, acc_cp, c, rbase);
            float av = tanhf(bias_s[c]);
            #pragma unroll
            for (int j = 0; j < 8; j++) {
                g_cat[(size_t)(row0 + rbase + j) * (2 * RDIM) + RDIM + c0 + c] = tanhf(acc_cp[j]);
                g_cat[(size_t)(row0 + rbase + j) * (2 * RDIM) + c0 + c] = av;
            }
        }
        grid_barrier();

        // ================= Phase B =================
        // S2: m = tanh(cat @ Wm + bm)
        {
            float acc_m[8];
            #pragma unroll
            for (int j = 0; j < 8; j++) acc_m[j] = bias_s[64 + c];
            gemm_pipe<8, false>(g_cat, 2 * RDIM, row0, Wm_s, (const float*)0,
                                As0, As1, acc_m, acc_m, c, rbase);
            #pragma unroll
            for (int j = 0; j < 8; j++)
                g_m[(size_t)(row0 + rbase + j) * RDIM + c0 + c] = tanhf(acc_m[j]);
        }
        // finalize out[t-1]: sum partials across the 8 col-tiles
        if (bj == 0 && t > 0 && tid < BM) {
            int n = row0 + tid;
            float s = br2v;
            #pragma unroll
            for (int jj = 0; jj < 8; jj++)
                s += __ldcg(&g_r1p[jj * NBATCH + n]);
            out[(size_t)(t - 1) * NBATCH + n] = s;
        }
        grid_barrier();

        // ================= Phase C =================
        // S3: h = tanh(m @ Whpost + bhpost)
        {
            float acc_h[8];
            #pragma unroll
            for (int j = 0; j < 8; j++) acc_h[j] = bias_s[96 + c];
            gemm_pipe<4, false>(g_m, RDIM, row0, Whpost_s, (const float*)0,
                                As0, As1, acc_h, acc_h, c, rbase);
            #pragma unroll
            for (int j = 0; j < 8; j++)
                g_h[(size_t)(row0 + rbase + j) * RDIM + c0 + c] = tanhf(acc_h[j]);
        }
        grid_barrier();
    }

    // ================= Epilogue: regressor for final step =================
    {
        float acc_r1[8];
        #pragma unroll
        for (int j = 0; j < 8; j++) acc_r1[j] = bias_s[128 + c];
        gemm_pipe<4, false>(g_h, RDIM, row0, Wr1_s, (const float*)0,
                            As0, As1, acc_r1, acc_r1, c, rbase);
        float w2 = bias_s[160 + c];
        #pragma unroll
        for (int j = 0; j < 8; j++) {
            float v = fmaxf(acc_r1[j], 0.f) * w2;
            #pragma unroll
            for (int off = 16; off > 0; off >>= 1)
                v += __shfl_down_sync(0xffffffffu, v, off);
            if (c == 0) g_r1p[bj * NBATCH + row0 + rbase + j] = v;
        }
    }
    grid_barrier();
    if (bj == 0 && tid < BM) {
        int n = row0 + tid;
        float s = br2v;
        #pragma unroll
        for (int jj = 0; jj < 8; jj++)
            s += __ldcg(&g_r1p[jj * NBATCH + n]);
        out[(size_t)(T_STEPS - 1) * NBATCH + n] = s;
    }
}

extern "C" void kernel_launch(void* const* d_in, const int* in_sizes, int n_in,
                              void* d_out, int out_size)
{
    (void)in_sizes; (void)n_in; (void)out_size;
    const float* inputs = (const float*)d_in[0];
    const float* Whp    = (const float*)d_in[1];
    const float* bhp    = (const float*)d_in[2];
    const float* Wcp    = (const float*)d_in[3];
    const float* bcp    = (const float*)d_in[4];
    const float* Wm     = (const float*)d_in[5];
    const float* bm     = (const float*)d_in[6];
    const float* Whpost = (const float*)d_in[7];
    const float* bhpost = (const float*)d_in[8];
    const float* Wr1    = (const float*)d_in[9];
    const float* br1    = (const float*)d_in[10];
    const float* Wr2    = (const float*)d_in[11];
    const float* br2    = (const float*)d_in[12];
    float* out = (float*)d_out;

    // dynamic smem: weights 43008 + bias 192 + 3*4096 staging = 55488 floats
    const size_t smem_bytes = (size_t)55488 * sizeof(float);
    cudaFuncSetAttribute(recurrent_kernel,
                         cudaFuncAttributeMaxDynamicSharedMemorySize,
                         (int)smem_bytes);

    recurrent_kernel<<<NCTA, NTHR, smem_bytes>>>(
        inputs, Whp, bhp, Wcp, bcp, Wm, bm, Whpost, bhpost,
        Wr1, br1, Wr2, br2, out);
}

// round 4
// speedup vs baseline: 1.1790x; 1.1790x over previous
#include <cuda_runtime.h>
#include <math.h>
#include <stdint.h>

// Problem constants
#define T_STEPS 512
#define NBATCH  1024
#define IDIM    64
#define RDIM    256
#define NCTA    128
#define NTHR    512
#define BM      64   // batch rows per CTA
#define BN      32   // output cols per CTA

typedef unsigned long long u64;

// -------- global scratch (pair-interleaved activation layout) --------
// elem(row,k) lives at [(row>>1)*2*ld + k*2 + (row&1)]
__device__ float g_h[NBATCH * RDIM];       // hidden state, pair layout ld=256
__device__ float g_cat[NBATCH * 2 * RDIM]; // concat buffer, pair layout ld=512
__device__ float g_m[NBATCH * RDIM];       // meshup out, pair layout ld=256
__device__ float g_r1p[8 * NBATCH];        // regressor partials per col-tile
__device__ unsigned g_bar_count = 0;
__device__ unsigned g_bar_gen = 0;

// -------- packed f32x2 helpers --------
__device__ __forceinline__ u64 dup2(float w) {
    u64 r; asm("mov.b64 %0, {%1, %1};" : "=l"(r) : "f"(w)); return r;
}
__device__ __forceinline__ void ffma2(u64& d, u64 a, u64 b) {
    asm("fma.rn.f32x2 %0, %1, %2, %0;" : "+l"(d) : "l"(a), "l"(b));
}
__device__ __forceinline__ float2 unpack2(u64 v) {
    float2 f; asm("mov.b64 {%0, %1}, %2;" : "=f"(f.x), "=f"(f.y) : "l"(v)); return f;
}

// -------- cp.async helpers (L1-bypass: cross-CTA producer/consumer) --------
__device__ __forceinline__ void cp_async16(float* sdst, const float* gsrc) {
    unsigned s = (unsigned)__cvta_generic_to_shared(sdst);
    asm volatile("cp.async.cg.shared.global [%0], [%1], 16;" :: "r"(s), "l"(gsrc));
}
__device__ __forceinline__ void cp_commit() { asm volatile("cp.async.commit_group;"); }
template <int N>
__device__ __forceinline__ void cp_wait() {
    asm volatile("cp.async.wait_group %0;" :: "n"(N));
}

// -------- grid-wide sense-reversing barrier --------
__device__ __forceinline__ void grid_barrier() {
    __threadfence();
    __syncthreads();
    if (threadIdx.x == 0) {
        unsigned g = *((volatile unsigned*)&g_bar_gen);
        unsigned old = atomicAdd(&g_bar_count, 1u);
        if (old == NCTA - 1) {
            g_bar_count = 0;
            __threadfence();
            *((volatile unsigned*)&g_bar_gen) = g + 1;
        } else {
            unsigned cur;
            do {
                asm volatile("ld.acquire.gpu.global.u32 %0, [%1];"
                             : "=r"(cur) : "l"(&g_bar_gen));
            } while (cur == g);
        }
    }
    __syncthreads();
}

// -------- stage one 32-pair x 64-k chunk from pair-layout global --------
// As layout: As[p*128 + k*2 + e], 4096 floats.
__device__ __forceinline__ void stage_pair(float* As, const float* __restrict__ G,
                                           int ld2, int pair0, int k0) {
    #pragma unroll
    for (int i = threadIdx.x; i < 1024; i += NTHR) {
        int p = i >> 5;       // pair 0..31
        int q = i & 31;       // 16B index within 512B pair-row
        cp_async16(As + p * 128 + q * 4,
                   G + (size_t)(pair0 + p) * ld2 + k0 * 2 + q * 4);
    }
    cp_commit();
}

// -------- compute one staged 64-k chunk --------
// Each thread: 2 row-pairs (p0, p0+1) x 1 col (c). acc = packed f32x2 per pair.
template <bool FUSE2>
__device__ __forceinline__ void compute_pair(
    const float* __restrict__ As,
    const float* __restrict__ Ws1, const float* __restrict__ Ws2,
    int k0, u64 acc1[2], u64 acc2[2], int c, int p0)
{
    const float* a0 = As + p0 * 128;
    const float* a1 = a0 + 128;
    #pragma unroll
    for (int k = 0; k < 64; k += 2) {
        ulonglong2 A0 = *(const ulonglong2*)(a0 + k * 2);   // {k, k+1} pair p0 (broadcast)
        ulonglong2 A1 = *(const ulonglong2*)(a1 + k * 2);   // {k, k+1} pair p0+1
        u64 w0 = dup2(Ws1[(k0 + k) * BN + c]);
        u64 w1 = dup2(Ws1[(k0 + k + 1) * BN + c]);
        ffma2(acc1[0], A0.x, w0); ffma2(acc1[1], A1.x, w0);
        ffma2(acc1[0], A0.y, w1); ffma2(acc1[1], A1.y, w1);
        if constexpr (FUSE2) {
            u64 v0 = dup2(Ws2[(k0 + k) * BN + c]);
            u64 v1 = dup2(Ws2[(k0 + k + 1) * BN + c]);
            ffma2(acc2[0], A0.x, v0); ffma2(acc2[1], A1.x, v0);
            ffma2(acc2[0], A0.y, v1); ffma2(acc2[1], A1.y, v1);
        }
    }
}

// -------- double-buffered pipelined GEMM over NCH 64-k chunks --------
template <int NCH, bool FUSE2>
__device__ __forceinline__ void gemm_pipe(
    const float* __restrict__ G, int ld2, int pair0,
    const float* __restrict__ Ws1, const float* __restrict__ Ws2,
    float* As0, float* As1, u64 acc1[2], u64 acc2[2], int c, int p0)
{
    stage_pair(As0, G, ld2, pair0, 0);
    if (NCH > 1) stage_pair(As1, G, ld2, pair0, 64);
    #pragma unroll
    for (int i = 0; i < NCH; i++) {
        if (i + 1 < NCH) cp_wait<1>(); else cp_wait<0>();
        __syncthreads();
        compute_pair<FUSE2>((i & 1) ? As1 : As0, Ws1, Ws2, i * 64, acc1, acc2, c, p0);
        __syncthreads();
        if (i + 2 < NCH) stage_pair((i & 1) ? As1 : As0, G, ld2, pair0, (i + 2) * 64);
    }
}

__global__ void __launch_bounds__(NTHR, 1)
recurrent_kernel(const float* __restrict__ inputs,
                 const float* __restrict__ Whp, const float* __restrict__ bhp,
                 const float* __restrict__ Wcp, const float* __restrict__ bcp,
                 const float* __restrict__ Wm,  const float* __restrict__ bm,
                 const float* __restrict__ Whpost, const float* __restrict__ bhpost,
                 const float* __restrict__ Wr1, const float* __restrict__ br1,
                 const float* __restrict__ Wr2, const float* __restrict__ br2,
                 float* __restrict__ out)
{
    extern __shared__ float smem[];
    float* Whp_s    = smem;                   // 256*32
    float* Wm_s     = Whp_s    + 256 * BN;    // 512*32
    float* Whpost_s = Wm_s     + 512 * BN;    // 256*32
    float* Wr1_s    = Whpost_s + 256 * BN;    // 256*32
    float* Wcp_s    = Wr1_s    + 256 * BN;    // 64*32
    float* bias_s   = Wcp_s    + 64 * BN;     // 192 floats
    float* As0      = bias_s   + 192;         // 4096
    float* As1      = As0      + 4096;        // 4096
    float* Xs       = As1      + 4096;        // 4096

    const int tid   = threadIdx.x;
    const int wid   = tid >> 5;
    const int bi    = blockIdx.x >> 3;   // batch-row tile 0..15
    const int bj    = blockIdx.x & 7;    // col tile 0..7
    const int row0  = bi * BM;
    const int pairg = row0 >> 1;         // global pair base for h/m (ld2=512)
    const int c0    = bj * BN;
    const int c     = tid & 31;          // output col within tile
    const int p0    = wid * 2;           // this warp's first local pair

    // ---- load resident weight slices ----
    for (int i = tid; i < 256 * BN; i += NTHR) {
        int k = i >> 5, cc = i & 31;
        Whp_s[i]    = Whp[k * RDIM + c0 + cc];
        Whpost_s[i] = Whpost[k * RDIM + c0 + cc];
        Wr1_s[i]    = Wr1[k * RDIM + c0 + cc];
    }
    for (int i = tid; i < 512 * BN; i += NTHR)
        Wm_s[i] = Wm[(i >> 5) * RDIM + c0 + (i & 31)];
    for (int i = tid; i < 64 * BN; i += NTHR)
        Wcp_s[i] = Wcp[(i >> 5) * RDIM + c0 + (i & 31)];
    if (tid < 32) {
        bias_s[tid]       = bhp[c0 + tid];
        bias_s[32 + tid]  = bcp[c0 + tid];
        bias_s[64 + tid]  = bm[c0 + tid];
        bias_s[96 + tid]  = bhpost[c0 + tid];
        bias_s[128 + tid] = br1[c0 + tid];
        bias_s[160 + tid] = Wr2[c0 + tid];   // Wr2 is (256,1)
    }
    const float br2v = __ldg(br2);
    __syncthreads();

    for (int t = 0; t < T_STEPS; t++) {
        // ================= Phase A =================
        // S1: a = tanh(h @ Whp + bhp) -> cat[:, 0:256]
        // S4 (lagged): r1 = relu(h @ Wr1 + br1) -> partials of r1 @ Wr2
        // S0: tcp = tanh(x_t @ Wcp + bcp) -> cat[:, 256:512]
        {
            u64 acc_cp[2];
            acc_cp[0] = acc_cp[1] = dup2(bias_s[32 + c]);

            if (t > 0) {
                stage_pair(As0, g_h, 512, pairg, 0);    // group
                stage_pair(As1, g_h, 512, pairg, 64);   // group
            }
            // stage x_t via LDG + pair-interleaved STS (standard input layout)
            {
                const float* xg = inputs + (size_t)t * NBATCH * IDIM;
                #pragma unroll
                for (int i = tid; i < 1024; i += NTHR) {
                    int r = i >> 4;
                    int kk = (i & 15) << 2;
                    float4 v = *(const float4*)(xg + (size_t)(row0 + r) * IDIM + kk);
                    float* xd = Xs + (r >> 1) * 128 + (r & 1);
                    xd[(kk + 0) * 2] = v.x;
                    xd[(kk + 1) * 2] = v.y;
                    xd[(kk + 2) * 2] = v.z;
                    xd[(kk + 3) * 2] = v.w;
                }
            }
            __syncthreads();
            compute_pair<false>(Xs, Wcp_s, (const float*)0, 0, acc_cp, acc_cp, c, p0);
            #pragma unroll
            for (int j = 0; j < 2; j++) {
                float2 f = unpack2(acc_cp[j]);
                size_t base = (size_t)(pairg + p0 + j) * 1024 + (size_t)(RDIM + c0 + c) * 2;
                g_cat[base + 0] = tanhf(f.x);
                g_cat[base + 1] = tanhf(f.y);
            }

            if (t > 0) {
                u64 acc_a[2], acc_r1[2];
                acc_a[0]  = acc_a[1]  = dup2(bias_s[c]);
                acc_r1[0] = acc_r1[1] = dup2(bias_s[128 + c]);
                #pragma unroll
                for (int i = 0; i < 4; i++) {
                    if (i + 1 < 4) cp_wait<1>(); else cp_wait<0>();
                    __syncthreads();
                    compute_pair<true>((i & 1) ? As1 : As0, Whp_s, Wr1_s, i * 64,
                                       acc_a, acc_r1, c, p0);
                    __syncthreads();
                    if (i + 2 < 4) stage_pair((i & 1) ? As1 : As0, g_h, 512, pairg, (i + 2) * 64);
                }
                float w2 = bias_s[160 + c];
                #pragma unroll
                for (int j = 0; j < 2; j++) {
                    float2 fa = unpack2(acc_a[j]);
                    size_t base = (size_t)(pairg + p0 + j) * 1024 + (size_t)(c0 + c) * 2;
                    g_cat[base + 0] = tanhf(fa.x);
                    g_cat[base + 1] = tanhf(fa.y);
                    float2 fr = unpack2(acc_r1[j]);
                    float v0 = fmaxf(fr.x, 0.f) * w2;
                    float v1 = fmaxf(fr.y, 0.f) * w2;
                    #pragma unroll
                    for (int off = 16; off > 0; off >>= 1) {
                        v0 += __shfl_down_sync(0xffffffffu, v0, off);
                        v1 += __shfl_down_sync(0xffffffffu, v1, off);
                    }
                    if (c == 0) {
                        int r = row0 + 4 * wid + 2 * j;
                        g_r1p[bj * NBATCH + r]     = v0;
                        g_r1p[bj * NBATCH + r + 1] = v1;
                    }
                }
            } else {
                // h0 == 0 -> a = tanh(bhp), uniform over rows
                float av = tanhf(bias_s[c]);
                #pragma unroll
                for (int j = 0; j < 2; j++) {
                    size_t base = (size_t)(pairg + p0 + j) * 1024 + (size_t)(c0 + c) * 2;
                    g_cat[base + 0] = av;
                    g_cat[base + 1] = av;
                }
            }
        }
        grid_barrier();

        // ================= Phase B =================
        // S2: m = tanh(cat @ Wm + bm)
        {
            u64 acc_m[2];
            acc_m[0] = acc_m[1] = dup2(bias_s[64 + c]);
            gemm_pipe<8, false>(g_cat, 1024, pairg, Wm_s, (const float*)0,
                                As0, As1, acc_m, acc_m, c, p0);
            #pragma unroll
            for (int j = 0; j < 2; j++) {
                float2 f = unpack2(acc_m[j]);
                size_t base = (size_t)(pairg + p0 + j) * 512 + (size_t)(c0 + c) * 2;
                g_m[base + 0] = tanhf(f.x);
                g_m[base + 1] = tanhf(f.y);
            }
        }
        // finalize out[t-1]: sum partials across the 8 col-tiles
        if (bj == 0 && t > 0 && tid < BM) {
            int n = row0 + tid;
            float s = br2v;
            #pragma unroll
            for (int jj = 0; jj < 8; jj++)
                s += __ldcg(&g_r1p[jj * NBATCH + n]);
            out[(size_t)(t - 1) * NBATCH + n] = s;
        }
        grid_barrier();

        // ================= Phase C =================
        // S3: h = tanh(m @ Whpost + bhpost)
        {
            u64 acc_h[2];
            acc_h[0] = acc_h[1] = dup2(bias_s[96 + c]);
            gemm_pipe<4, false>(g_m, 512, pairg, Whpost_s, (const float*)0,
                                As0, As1, acc_h, acc_h, c, p0);
            #pragma unroll
            for (int j = 0; j < 2; j++) {
                float2 f = unpack2(acc_h[j]);
                size_t base = (size_t)(pairg + p0 + j) * 512 + (size_t)(c0 + c) * 2;
                g_h[base + 0] = tanhf(f.x);
                g_h[base + 1] = tanhf(f.y);
            }
        }
        grid_barrier();
    }

    // ================= Epilogue: regressor for final step =================
    {
        u64 acc_r1[2];
        acc_r1[0] = acc_r1[1] = dup2(bias_s[128 + c]);
        gemm_pipe<4, false>(g_h, 512, pairg, Wr1_s, (const float*)0,
                            As0, As1, acc_r1, acc_r1, c, p0);
        float w2 = bias_s[160 + c];
        #pragma unroll
        for (int j = 0; j < 2; j++) {
            float2 fr = unpack2(acc_r1[j]);
            float v0 = fmaxf(fr.x, 0.f) * w2;
            float v1 = fmaxf(fr.y, 0.f) * w2;
            #pragma unroll
            for (int off = 16; off > 0; off >>= 1) {
                v0 += __shfl_down_sync(0xffffffffu, v0, off);
                v1 += __shfl_down_sync(0xffffffffu, v1, off);
            }
            if (c == 0) {
                int r = row0 + 4 * wid + 2 * j;
                g_r1p[bj * NBATCH + r]     = v0;
                g_r1p[bj * NBATCH + r + 1] = v1;
            }
        }
    }
    grid_barrier();
    if (bj == 0 && tid < BM) {
        int n = row0 + tid;
        float s = br2v;
        #pragma unroll
        for (int jj = 0; jj < 8; jj++)
            s += __ldcg(&g_r1p[jj * NBATCH + n]);
        out[(size_t)(T_STEPS - 1) * NBATCH + n] = s;
    }
}

extern "C" void kernel_launch(void* const* d_in, const int* in_sizes, int n_in,
                              void* d_out, int out_size)
{
    (void)in_sizes; (void)n_in; (void)out_size;
    const float* inputs = (const float*)d_in[0];
    const float* Whp    = (const float*)d_in[1];
    const float* bhp    = (const float*)d_in[2];
    const float* Wcp    = (const float*)d_in[3];
    const float* bcp    = (const float*)d_in[4];
    const float* Wm     = (const float*)d_in[5];
    const float* bm     = (const float*)d_in[6];
    const float* Whpost = (const float*)d_in[7];
    const float* bhpost = (const float*)d_in[8];
    const float* Wr1    = (const float*)d_in[9];
    const float* br1    = (const float*)d_in[10];
    const float* Wr2    = (const float*)d_in[11];
    const float* br2    = (const float*)d_in[12];
    float* out = (float*)d_out;

    // dynamic smem: weights 43008 + bias 192 + 3*4096 staging = 55488 floats
    const size_t smem_bytes = (size_t)55488 * sizeof(float);
    cudaFuncSetAttribute(recurrent_kernel,
                         cudaFuncAttributeMaxDynamicSharedMemorySize,
                         (int)smem_bytes);

    recurrent_kernel<<<NCTA, NTHR, smem_bytes>>>(
        inputs, Whp, bhp, Wcp, bcp, Wm, bm, Whpost, bhpost,
        Wr1, br1, Wr2, br2, out);
}

// round 6
// speedup vs baseline: 1.5300x; 1.2977x over previous
#include <cuda_runtime.h>
#include <math.h>
#include <stdint.h>

// Problem constants
#define T_STEPS 512
#define NBATCH  1024
#define IDIM    64
#define RDIM    256
#define NCTA    128
#define NTHR    256
#define BM      64   // batch rows per CTA
#define BN      32   // output cols per CTA

typedef unsigned long long u64;

// -------- global scratch --------
// Activations in per-row-tile k-major pair-packed layout:
//   elem(tile bi, k, row r=2*pl+e) at  base(bi) + k*64 + pl*2 + e
__device__ float g_h[NBATCH * RDIM];        // [16][256][32][2]
__device__ float g_cat[NBATCH * 2 * RDIM];  // [16][512][32][2]
__device__ float g_m[NBATCH * RDIM];        // [16][256][32][2]
__device__ float g_r1p2[32 * NBATCH];       // regressor partials [bj*4+wc][1024]
__device__ unsigned g_bar_count = 0;
__device__ unsigned g_bar_gen = 0;

// -------- packed f32x2 helpers --------
__device__ __forceinline__ u64 dup2(float w) {
    u64 r; asm("mov.b64 %0, {%1, %1};" : "=l"(r) : "f"(w)); return r;
}
__device__ __forceinline__ void ffma2(u64& d, u64 a, u64 b) {
    asm("fma.rn.f32x2 %0, %1, %2, %0;" : "+l"(d) : "l"(a), "l"(b));
}
__device__ __forceinline__ float2 unpack2(u64 v) {
    float2 f; asm("mov.b64 {%0, %1}, %2;" : "=f"(f.x), "=f"(f.y) : "l"(v)); return f;
}

// -------- cp.async helpers (L1-bypass for cross-CTA coherence) --------
__device__ __forceinline__ void cp_async16(float* sdst, const float* gsrc) {
    unsigned s = (unsigned)__cvta_generic_to_shared(sdst);
    asm volatile("cp.async.cg.shared.global [%0], [%1], 16;" :: "r"(s), "l"(gsrc));
}
__device__ __forceinline__ void cp_commit() { asm volatile("cp.async.commit_group;"); }
template <int N>
__device__ __forceinline__ void cp_wait() {
    asm volatile("cp.async.wait_group %0;" :: "n"(N));
}

// -------- grid-wide sense-reversing barrier --------
__device__ __forceinline__ void grid_barrier() {
    __threadfence();
    __syncthreads();
    if (threadIdx.x == 0) {
        unsigned g = *((volatile unsigned*)&g_bar_gen);
        unsigned old = atomicAdd(&g_bar_count, 1u);
        if (old == NCTA - 1) {
            g_bar_count = 0;
            __threadfence();
            *((volatile unsigned*)&g_bar_gen) = g + 1;
        } else {
            unsigned cur;
            do {
                asm volatile("ld.acquire.gpu.global.u32 %0, [%1];"
                             : "=r"(cur) : "l"(&g_bar_gen));
            } while (cur == g);
        }
    }
    __syncthreads();
}

// -------- stage one contiguous 16KB chunk (64k x 64 floats), one group --------
__device__ __forceinline__ void stage16k(float* buf, const float* __restrict__ g) {
    int u = threadIdx.x;
    #pragma unroll
    for (int i = 0; i < 4; i++, u += NTHR)
        cp_async16(buf + u * 4, g + u * 4);
    cp_commit();
}

// -------- compute one staged 64k chunk --------
// As: [k][pair][e] (64 k-rows x 64 floats). Thread: pairs plbase..+1, cols cc..+1.
// acc layout: a[0]=p0c0, a[1]=p1c0, a[2]=p0c1, a[3]=p1c1 (packed over rows).
template <bool FUSE2>
__device__ __forceinline__ void compute_chunk(
    const float* __restrict__ As,
    const float* __restrict__ w1p, const float* __restrict__ w2p,
    u64 a1[4], u64 a2[4], int plbase, int cc)
{
    #pragma unroll 8
    for (int k2 = 0; k2 < 32; k2++) {
        const float* arow = As + (k2 * 2) * 64 + plbase * 2;
        ulonglong2 A0 = *(const ulonglong2*)(arow);        // k even: pairs pl, pl+1
        ulonglong2 A1 = *(const ulonglong2*)(arow + 64);   // k odd
        float4 w = *(const float4*)(w1p + k2 * 64 + cc * 2);
        u64 w00 = dup2(w.x), w01 = dup2(w.y), w10 = dup2(w.z), w11 = dup2(w.w);
        ffma2(a1[0], A0.x, w00); ffma2(a1[1], A0.y, w00);
        ffma2(a1[2], A0.x, w10); ffma2(a1[3], A0.y, w10);
        ffma2(a1[0], A1.x, w01); ffma2(a1[1], A1.y, w01);
        ffma2(a1[2], A1.x, w11); ffma2(a1[3], A1.y, w11);
        if constexpr (FUSE2) {
            float4 v = *(const float4*)(w2p + k2 * 64 + cc * 2);
            u64 v00 = dup2(v.x), v01 = dup2(v.y), v10 = dup2(v.z), v11 = dup2(v.w);
            ffma2(a2[0], A0.x, v00); ffma2(a2[1], A0.y, v00);
            ffma2(a2[2], A0.x, v10); ffma2(a2[3], A0.y, v10);
            ffma2(a2[0], A1.x, v01); ffma2(a2[1], A1.y, v01);
            ffma2(a2[2], A1.x, v11); ffma2(a2[3], A1.y, v11);
        }
    }
}

// -------- pipelined GEMM over NCH 64k chunks (3-buffer ring, 1 sync/chunk) ----
template <int NCH, bool FUSE2>
__device__ __forceinline__ void gemm_pipe(
    const float* __restrict__ gbase,
    const float* __restrict__ W1, const float* __restrict__ W2,
    float* bufs, u64 a1[4], u64 a2[4], int plbase, int cc)
{
    stage16k(bufs,        gbase);
    stage16k(bufs + 4096, gbase + 4096);
    #pragma unroll
    for (int i = 0; i < NCH; i++) {
        if (i < NCH - 1) cp_wait<1>(); else cp_wait<0>();
        __syncthreads();
        if (i + 2 < NCH) stage16k(bufs + ((i + 2) % 3) * 4096, gbase + (i + 2) * 4096);
        compute_chunk<FUSE2>(bufs + (i % 3) * 4096, W1 + i * 2048, W2 + i * 2048,
                             a1, a2, plbase, cc);
    }
}

__global__ void __launch_bounds__(NTHR, 1)
recurrent_kernel(const float* __restrict__ inputs,
                 const float* __restrict__ Whp, const float* __restrict__ bhp,
                 const float* __restrict__ Wcp, const float* __restrict__ bcp,
                 const float* __restrict__ Wm,  const float* __restrict__ bm,
                 const float* __restrict__ Whpost, const float* __restrict__ bhpost,
                 const float* __restrict__ Wr1, const float* __restrict__ br1,
                 const float* __restrict__ Wr2, const float* __restrict__ br2,
                 float* __restrict__ out)
{
    extern __shared__ float smem[];
    float* Whp_p    = smem;                 // 8192  (256k packed)
    float* Wr1_p    = Whp_p    + 8192;      // 8192
    float* Wm_p     = Wr1_p    + 8192;      // 16384 (512k packed)
    float* Whpost_p = Wm_p     + 16384;     // 8192
    float* Wcp_p    = Whpost_p + 8192;      // 2048  (64k packed)
    float* bias_s   = Wcp_p    + 2048;      // 192
    float* bufs     = bias_s   + 192;       // 3 x 4096

    const int tid  = threadIdx.x;
    const int wid  = tid >> 5;
    const int lane = tid & 31;
    const int wr = wid & 1;          // row half (32 rows)
    const int wc = wid >> 1;         // col group (8 cols), 0..3
    const int lr = lane >> 2;        // lane row  0..7
    const int lc = lane & 3;         // lane col  0..3
    const int plbase = wr * 16 + lr * 2;   // first local pair (of 2)
    const int cc     = wc * 8 + lc * 2;    // first local col (of 2)

    const int bi   = blockIdx.x >> 3;
    const int bj   = blockIdx.x & 7;
    const int row0 = bi * BM;
    const int c0   = bj * BN;

    const int hbase   = bi * (RDIM * BM);       // 16384 floats per tile
    const int catbase = bi * (2 * RDIM * BM);   // 32768
    float* Xs; // alias of bufs+2 for S0

    // ---- build packed weight slices: Wp[(k>>1)*64 + col*2 + (k&1)] ----
    for (int i = tid; i < 256 * BN; i += NTHR) {
        int k = i >> 5, col = i & 31;
        int d = (k >> 1) * 64 + col * 2 + (k & 1);
        Whp_p[d]    = Whp[k * RDIM + c0 + col];
        Wr1_p[d]    = Wr1[k * RDIM + c0 + col];
        Whpost_p[d] = Whpost[k * RDIM + c0 + col];
    }
    for (int i = tid; i < 512 * BN; i += NTHR) {
        int k = i >> 5, col = i & 31;
        Wm_p[(k >> 1) * 64 + col * 2 + (k & 1)] = Wm[k * RDIM + c0 + col];
    }
    for (int i = tid; i < 64 * BN; i += NTHR) {
        int k = i >> 5, col = i & 31;
        Wcp_p[(k >> 1) * 64 + col * 2 + (k & 1)] = Wcp[k * RDIM + c0 + col];
    }
    if (tid < 32) {
        bias_s[tid]       = bhp[c0 + tid];
        bias_s[32 + tid]  = bcp[c0 + tid];
        bias_s[64 + tid]  = bm[c0 + tid];
        bias_s[96 + tid]  = bhpost[c0 + tid];
        bias_s[128 + tid] = br1[c0 + tid];
        bias_s[160 + tid] = Wr2[c0 + tid];
    }
    const float br2v = __ldg(br2);
    __syncthreads();

    for (int t = 0; t < T_STEPS; t++) {
        // ================= Phase A =================
        // stage x_t (row-major, XOR-swizzled slots) into buf2
        Xs = bufs + 2 * 4096;
        {
            const float* xg = inputs + (size_t)t * NBATCH * IDIM + (size_t)row0 * IDIM;
            int u = tid;
            #pragma unroll
            for (int i = 0; i < 4; i++, u += NTHR) {
                int r = u >> 4, s = u & 15;
                cp_async16(Xs + r * 64 + ((s ^ ((r >> 2) & 7)) << 2), xg + r * 64 + s * 4);
            }
            cp_commit();
        }
        if (t > 0) {
            stage16k(bufs,        g_h + hbase);
            stage16k(bufs + 4096, g_h + hbase + 4096);
            cp_wait<2>();
        } else {
            cp_wait<0>();
        }
        __syncthreads();

        // ---- S0: tcp = tanh(x @ Wcp + bcp) -> cat[:, 256:512] (scalar path) ----
        {
            float aS[4][2];
            #pragma unroll
            for (int j = 0; j < 4; j++) {
                aS[j][0] = bias_s[32 + cc];
                aS[j][1] = bias_s[32 + cc + 1];
            }
            #pragma unroll 4
            for (int k4 = 0; k4 < 16; k4++) {
                float4 wA = *(const float4*)(Wcp_p + (2 * k4) * 64 + cc * 2);
                float4 wB = *(const float4*)(Wcp_p + (2 * k4 + 1) * 64 + cc * 2);
                #pragma unroll
                for (int j = 0; j < 4; j++) {
                    int r = wr * 32 + lr * 4 + j;
                    float4 a = *(const float4*)(Xs + r * 64 + ((k4 ^ lr) << 2));
                    aS[j][0] = fmaf(a.x, wA.x, aS[j][0]);
                    aS[j][0] = fmaf(a.y, wA.y, aS[j][0]);
                    aS[j][0] = fmaf(a.z, wB.x, aS[j][0]);
                    aS[j][0] = fmaf(a.w, wB.y, aS[j][0]);
                    aS[j][1] = fmaf(a.x, wA.z, aS[j][1]);
                    aS[j][1] = fmaf(a.y, wA.w, aS[j][1]);
                    aS[j][1] = fmaf(a.z, wB.z, aS[j][1]);
                    aS[j][1] = fmaf(a.w, wB.w, aS[j][1]);
                }
            }
            #pragma unroll
            for (int ci = 0; ci < 2; ci++)
                #pragma unroll
                for (int p = 0; p < 2; p++) {
                    float2 v = make_float2(tanhf(aS[2 * p][ci]), tanhf(aS[2 * p + 1][ci]));
                    *(float2*)(g_cat + catbase + (RDIM + c0 + cc + ci) * 64
                               + (plbase + p) * 2) = v;
                }
        }

        if (t > 0) {
            // ---- S1 + S4 fused: a = tanh(h@Whp+bhp); r1acc = h@Wr1+br1 ----
            u64 acc_a[4], acc_r[4];
            acc_a[0] = acc_a[1] = dup2(bias_s[cc]);
            acc_a[2] = acc_a[3] = dup2(bias_s[cc + 1]);
            acc_r[0] = acc_r[1] = dup2(bias_s[128 + cc]);
            acc_r[2] = acc_r[3] = dup2(bias_s[128 + cc + 1]);
            #pragma unroll
            for (int i = 0; i < 4; i++) {
                if (i < 3) cp_wait<1>(); else cp_wait<0>();
                __syncthreads();
                if (i + 2 < 4) stage16k(bufs + ((i + 2) % 3) * 4096,
                                        g_h + hbase + (i + 2) * 4096);
                compute_chunk<true>(bufs + (i % 3) * 4096, Whp_p + i * 2048,
                                    Wr1_p + i * 2048, acc_a, acc_r, plbase, cc);
            }
            #pragma unroll
            for (int ci = 0; ci < 2; ci++)
                #pragma unroll
                for (int p = 0; p < 2; p++) {
                    float2 f = unpack2(acc_a[ci * 2 + p]);
                    *(float2*)(g_cat + catbase + (c0 + cc + ci) * 64 + (plbase + p) * 2)
                        = make_float2(tanhf(f.x), tanhf(f.y));
                }
            // S4 reduce: v[row] = sum_cols relu(acc)*Wr2[col]
            {
                float w20 = bias_s[160 + cc], w21 = bias_s[160 + cc + 1];
                float2 r00 = unpack2(acc_r[0]), r10 = unpack2(acc_r[1]);
                float2 r01 = unpack2(acc_r[2]), r11 = unpack2(acc_r[3]);
                float v0 = fmaxf(r00.x, 0.f) * w20 + fmaxf(r01.x, 0.f) * w21;
                float v1 = fmaxf(r00.y, 0.f) * w20 + fmaxf(r01.y, 0.f) * w21;
                float v2 = fmaxf(r10.x, 0.f) * w20 + fmaxf(r11.x, 0.f) * w21;
                float v3 = fmaxf(r10.y, 0.f) * w20 + fmaxf(r11.y, 0.f) * w21;
                #pragma unroll
                for (int off = 1; off <= 2; off <<= 1) {
                    v0 += __shfl_xor_sync(0xffffffffu, v0, off);
                    v1 += __shfl_xor_sync(0xffffffffu, v1, off);
                    v2 += __shfl_xor_sync(0xffffffffu, v2, off);
                    v3 += __shfl_xor_sync(0xffffffffu, v3, off);
                }
                if (lc == 0)
                    *(float4*)(g_r1p2 + (bj * 4 + wc) * NBATCH + row0 + wr * 32 + lr * 4)
                        = make_float4(v0, v1, v2, v3);
            }
        } else {
            // h0 == 0 -> cat[:,0:256] = tanh(bhp), uniform over rows
            #pragma unroll
            for (int ci = 0; ci < 2; ci++) {
                float av = tanhf(bias_s[cc + ci]);
                #pragma unroll
                for (int p = 0; p < 2; p++)
                    *(float2*)(g_cat + catbase + (c0 + cc + ci) * 64 + (plbase + p) * 2)
                        = make_float2(av, av);
            }
        }
        grid_barrier();

        // ================= Phase B: m = tanh(cat @ Wm + bm) =================
        {
            u64 acc[4];
            acc[0] = acc[1] = dup2(bias_s[64 + cc]);
            acc[2] = acc[3] = dup2(bias_s[64 + cc + 1]);
            gemm_pipe<8, false>(g_cat + catbase, Wm_p, Wm_p, bufs, acc, acc, plbase, cc);
            #pragma unroll
            for (int ci = 0; ci < 2; ci++)
                #pragma unroll
                for (int p = 0; p < 2; p++) {
                    float2 f = unpack2(acc[ci * 2 + p]);
                    *(float2*)(g_m + hbase + (c0 + cc + ci) * 64 + (plbase + p) * 2)
                        = make_float2(tanhf(f.x), tanhf(f.y));
                }
        }
        // finalize out[t-1]
        if (bj == 0 && t > 0 && tid < BM) {
            int n = row0 + tid;
            float s = br2v;
            #pragma unroll
            for (int q = 0; q < 32; q++)
                s += __ldcg(&g_r1p2[q * NBATCH + n]);
            out[(size_t)(t - 1) * NBATCH + n] = s;
        }
        grid_barrier();

        // ================= Phase C: h = tanh(m @ Whpost + bhpost) ============
        {
            u64 acc[4];
            acc[0] = acc[1] = dup2(bias_s[96 + cc]);
            acc[2] = acc[3] = dup2(bias_s[96 + cc + 1]);
            gemm_pipe<4, false>(g_m + hbase, Whpost_p, Whpost_p, bufs, acc, acc, plbase, cc);
            #pragma unroll
            for (int ci = 0; ci < 2; ci++)
                #pragma unroll
                for (int p = 0; p < 2; p++) {
                    float2 f = unpack2(acc[ci * 2 + p]);
                    *(float2*)(g_h + hbase + (c0 + cc + ci) * 64 + (plbase + p) * 2)
                        = make_float2(tanhf(f.x), tanhf(f.y));
                }
        }
        grid_barrier();
    }

    // ================= Epilogue: regressor for final step =================
    {
        u64 acc[4];
        acc[0] = acc[1] = dup2(bias_s[128 + cc]);
        acc[2] = acc[3] = dup2(bias_s[128 + cc + 1]);
        gemm_pipe<4, false>(g_h + hbase, Wr1_p, Wr1_p, bufs, acc, acc, plbase, cc);
        float w20 = bias_s[160 + cc], w21 = bias_s[160 + cc + 1];
        float2 r00 = unpack2(acc[0]), r10 = unpack2(acc[1]);
        float2 r01 = unpack2(acc[2]), r11 = unpack2(acc[3]);
        float v0 = fmaxf(r00.x, 0.f) * w20 + fmaxf(r01.x, 0.f) * w21;
        float v1 = fmaxf(r00.y, 0.f) * w20 + fmaxf(r01.y, 0.f) * w21;
        float v2 = fmaxf(r10.x, 0.f) * w20 + fmaxf(r11.x, 0.f) * w21;
        float v3 = fmaxf(r10.y, 0.f) * w20 + fmaxf(r11.y, 0.f) * w21;
        #pragma unroll
        for (int off = 1; off <= 2; off <<= 1) {
            v0 += __shfl_xor_sync(0xffffffffu, v0, off);
            v1 += __shfl_xor_sync(0xffffffffu, v1, off);
            v2 += __shfl_xor_sync(0xffffffffu, v2, off);
            v3 += __shfl_xor_sync(0xffffffffu, v3, off);
        }
        if (lc == 0)
            *(float4*)(g_r1p2 + (bj * 4 + wc) * NBATCH + row0 + wr * 32 + lr * 4)
                = make_float4(v0, v1, v2, v3);
    }
    grid_barrier();
    if (bj == 0 && tid < BM) {
        int n = row0 + tid;
        float s = br2v;
        #pragma unroll
        for (int q = 0; q < 32; q++)
            s += __ldcg(&g_r1p2[q * NBATCH + n]);
        out[(size_t)(T_STEPS - 1) * NBATCH + n] = s;
    }
}

extern "C" void kernel_launch(void* const* d_in, const int* in_sizes, int n_in,
                              void* d_out, int out_size)
{
    (void)in_sizes; (void)n_in; (void)out_size;
    const float* inputs = (const float*)d_in[0];
    const float* Whp    = (const float*)d_in[1];
    const float* bhp    = (const float*)d_in[2];
    const float* Wcp    = (const float*)d_in[3];
    const float* bcp    = (const float*)d_in[4];
    const float* Wm     = (const float*)d_in[5];
    const float* bm     = (const float*)d_in[6];
    const float* Whpost = (const float*)d_in[7];
    const float* bhpost = (const float*)d_in[8];
    const float* Wr1    = (const float*)d_in[9];
    const float* br1    = (const float*)d_in[10];
    const float* Wr2    = (const float*)d_in[11];
    const float* br2    = (const float*)d_in[12];
    float* out = (float*)d_out;

    // smem: packed weights 43008 + bias 192 + 3x4096 staging = 55488 floats
    const size_t smem_bytes = (size_t)55488 * sizeof(float);
    cudaFuncSetAttribute(recurrent_kernel,
                         cudaFuncAttributeMaxDynamicSharedMemorySize,
                         (int)smem_bytes);

    recurrent_kernel<<<NCTA, NTHR, smem_bytes>>>(
        inputs, Whp, bhp, Wcp, bcp, Wm, bm, Whpost, bhpost,
        Wr1, br1, Wr2, br2, out);
}